// round 1
// baseline (speedup 1.0000x reference)
#include <cuda_runtime.h>
#include <cstdint>

// Problem constants (fixed by the reference)
constexpr int D   = 256;
constexpr int NP  = 100000;   // n_pois
constexpr int NH  = 50000;    // n_hyperedges
constexpr int NNZC = 1600000; // nnz

// ---------------------------------------------------------------------------
// Scratch: __device__ globals (no cudaMalloc allowed)
// ---------------------------------------------------------------------------
__device__ float g_msg_tar[(size_t)NH * D];   // 51.2 MB
__device__ float g_msg_src[(size_t)NP * D];   // 102.4 MB
__device__ float g_embs1 [(size_t)NP * D];    // 102.4 MB
__device__ float g_w[3];

// ---------------------------------------------------------------------------
// softmax over the 3 layer-attention logits -> g_w
// ---------------------------------------------------------------------------
__global__ void softmax3_kernel(const float* __restrict__ att) {
    if (threadIdx.x == 0) {
        float a0 = att[0], a1 = att[1], a2 = att[2];
        float m  = fmaxf(a0, fmaxf(a1, a2));
        float e0 = expf(a0 - m), e1 = expf(a1 - m), e2 = expf(a2 - m);
        float s  = e0 + e1 + e2;
        g_w[0] = e0 / s; g_w[1] = e1 / s; g_w[2] = e2 / s;
    }
}

// ---------------------------------------------------------------------------
// zero a float buffer (float4 stores, grid-stride)
// ---------------------------------------------------------------------------
__global__ void zero_kernel(float4* __restrict__ p, int n4) {
    float4 z = make_float4(0.f, 0.f, 0.f, 0.f);
    for (int i = blockIdx.x * blockDim.x + threadIdx.x; i < n4;
         i += gridDim.x * blockDim.x)
        p[i] = z;
}

// ---------------------------------------------------------------------------
// COO SpMM: out[rows[e], :] += vals[e] * dense[cols[e], :]
// One warp per edge (grid-stride). Each lane handles 2x float4 (8 floats).
// Scatter uses red.global.add.v4.f32 (vector reduction, no return).
// ---------------------------------------------------------------------------
__global__ void __launch_bounds__(256)
spmm_kernel(float* __restrict__ out, const float* __restrict__ dense,
            const float* __restrict__ vals, const int* __restrict__ rows,
            const int* __restrict__ cols, int nnz) {
    const int lane = threadIdx.x & 31;
    int warp = (blockIdx.x * blockDim.x + threadIdx.x) >> 5;
    const int nw = (gridDim.x * blockDim.x) >> 5;

    for (int e = warp; e < nnz; e += nw) {
        const int   r = rows[e];
        const int   c = cols[e];
        const float v = vals[e];

        const float4* __restrict__ s =
            reinterpret_cast<const float4*>(dense + (size_t)c * D) + lane;
        float* dbase = out + (size_t)r * D + lane * 4;

        float4 x0 = s[0];
        float4 x1 = s[32];
        asm volatile("red.global.add.v4.f32 [%0], {%1, %2, %3, %4};"
                     :: "l"(dbase),
                        "f"(x0.x * v), "f"(x0.y * v), "f"(x0.z * v), "f"(x0.w * v)
                     : "memory");
        asm volatile("red.global.add.v4.f32 [%0], {%1, %2, %3, %4};"
                     :: "l"(dbase + 128),
                        "f"(x1.x * v), "f"(x1.y * v), "f"(x1.z * v), "f"(x1.w * v)
                     : "memory");
    }
}

// ---------------------------------------------------------------------------
// Layer-1 elementwise: embs1 = (relu(msg_src)*drop1[0] + pois) * drop2[0]
// ---------------------------------------------------------------------------
__global__ void __launch_bounds__(256)
ew1_kernel(const float4* __restrict__ pois, const float4* __restrict__ d1,
           const float4* __restrict__ d2, int n4) {
    const float4* __restrict__ ms = reinterpret_cast<const float4*>(g_msg_src);
    float4* __restrict__ e1 = reinterpret_cast<float4*>(g_embs1);
    for (int i = blockIdx.x * blockDim.x + threadIdx.x; i < n4;
         i += gridDim.x * blockDim.x) {
        float4 m = ms[i], p = pois[i], a = d1[i], b = d2[i];
        float4 r;
        r.x = (fmaxf(m.x, 0.f) * a.x + p.x) * b.x;
        r.y = (fmaxf(m.y, 0.f) * a.y + p.y) * b.y;
        r.z = (fmaxf(m.z, 0.f) * a.z + p.z) * b.z;
        r.w = (fmaxf(m.w, 0.f) * a.w + p.w) * b.w;
        e1[i] = r;
    }
}

// ---------------------------------------------------------------------------
// Final elementwise:
//   embs2 = (relu(msg_src)*drop1[1] + embs1) * drop2[1]
//   out   = w0*pois + w1*embs1 + w2*embs2
// ---------------------------------------------------------------------------
__global__ void __launch_bounds__(256)
final_kernel(float4* __restrict__ out, const float4* __restrict__ pois,
             const float4* __restrict__ d1, const float4* __restrict__ d2,
             int n4) {
    const float w0 = g_w[0], w1 = g_w[1], w2 = g_w[2];
    const float4* __restrict__ ms = reinterpret_cast<const float4*>(g_msg_src);
    const float4* __restrict__ e1 = reinterpret_cast<const float4*>(g_embs1);
    for (int i = blockIdx.x * blockDim.x + threadIdx.x; i < n4;
         i += gridDim.x * blockDim.x) {
        float4 m = ms[i], p = pois[i], a = d1[i], b = d2[i], e = e1[i];
        float4 r;
        r.x = w0 * p.x + w1 * e.x + w2 * ((fmaxf(m.x, 0.f) * a.x + e.x) * b.x);
        r.y = w0 * p.y + w1 * e.y + w2 * ((fmaxf(m.y, 0.f) * a.y + e.y) * b.y);
        r.z = w0 * p.z + w1 * e.z + w2 * ((fmaxf(m.z, 0.f) * a.z + e.z) * b.z);
        r.w = w0 * p.w + w1 * e.w + w2 * ((fmaxf(m.w, 0.f) * a.w + e.w) * b.w);
        out[i] = r;
    }
}

// ---------------------------------------------------------------------------
// kernel_launch — graph-capturable, allocation-free
// ---------------------------------------------------------------------------
extern "C" void kernel_launch(void* const* d_in, const int* in_sizes, int n_in,
                              void* d_out, int out_size) {
    const float* pois     = (const float*)d_in[0];
    const float* tar_vals = (const float*)d_in[1];
    const float* src_vals = (const float*)d_in[2];
    const float* att      = (const float*)d_in[3];
    const float* drop1    = (const float*)d_in[4];   // [2, NP, D]
    const float* drop2    = (const float*)d_in[5];   // [2, NP, D]
    const int*   tar_rows = (const int*)d_in[6];
    const int*   tar_cols = (const int*)d_in[7];
    const int*   src_rows = (const int*)d_in[8];
    const int*   src_cols = (const int*)d_in[9];
    float* out = (float*)d_out;

    float *p_mt = nullptr, *p_ms = nullptr, *p_e1 = nullptr;
    cudaGetSymbolAddress((void**)&p_mt, g_msg_tar);
    cudaGetSymbolAddress((void**)&p_ms, g_msg_src);
    cudaGetSymbolAddress((void**)&p_e1, g_embs1);

    const int ZB = 2048, ZT = 256;   // zero kernels
    const int SB = 4096, ST = 256;   // spmm: 32768 warps, ~49 edges/warp
    const int EB = 4096, ET = 256;   // elementwise

    const int n4p = NP * D / 4;      // 6.4M float4
    const int n4h = NH * D / 4;      // 3.2M float4

    softmax3_kernel<<<1, 32>>>(att);

    // ---- layer 1 ----
    zero_kernel<<<ZB, ZT>>>((float4*)p_mt, n4h);
    spmm_kernel<<<SB, ST>>>(p_mt, pois, tar_vals, tar_rows, tar_cols, NNZC);
    zero_kernel<<<ZB, ZT>>>((float4*)p_ms, n4p);
    spmm_kernel<<<SB, ST>>>(p_ms, p_mt, src_vals, src_rows, src_cols, NNZC);
    ew1_kernel<<<EB, ET>>>((const float4*)pois, (const float4*)drop1,
                           (const float4*)drop2, n4p);

    // ---- layer 2 ----
    zero_kernel<<<ZB, ZT>>>((float4*)p_mt, n4h);
    spmm_kernel<<<SB, ST>>>(p_mt, p_e1, tar_vals, tar_rows, tar_cols, NNZC);
    zero_kernel<<<ZB, ZT>>>((float4*)p_ms, n4p);
    spmm_kernel<<<SB, ST>>>(p_ms, p_mt, src_vals, src_rows, src_cols, NNZC);

    // ---- weighted combine (computes embs2 inline) ----
    final_kernel<<<EB, ET>>>((float4*)out, (const float4*)pois,
                             (const float4*)(drop1 + (size_t)NP * D),
                             (const float4*)(drop2 + (size_t)NP * D), n4p);
}

// round 4
// speedup vs baseline: 2.3551x; 2.3551x over previous
#include <cuda_runtime.h>
#include <cstdint>

// Problem constants (fixed by the reference)
constexpr int D    = 256;
constexpr int D4   = 64;       // float4 per row
constexpr int NP   = 100000;   // n_pois
constexpr int NH   = 50000;    // n_hyperedges
constexpr int NNZC = 1600000;  // nnz

constexpr int SCAN_TILE = 2048;    // elements per scan tile (1024 thr x 2)

// ---------------------------------------------------------------------------
// Scratch: __device__ globals (no cudaMalloc allowed)
// ---------------------------------------------------------------------------
__device__ int   g_offs_t[NH + 1];
__device__ int   g_cur_t [NH + 1];
__device__ int   g_offs_s[NP + 1];
__device__ int   g_cur_s [NP + 1];
__device__ int   g_tsum  [128];

__device__ int   g_cols_t[NNZC];
__device__ float g_vals_t[NNZC];
__device__ int   g_cols_s[NNZC];
__device__ float g_vals_s[NNZC];

__device__ float g_msg_tar[(size_t)NH * D];   // 51.2 MB
__device__ float g_embs1 [(size_t)NP * D];    // 102.4 MB
__device__ float g_w[3];

// ---------------------------------------------------------------------------
// softmax over the 3 layer-attention logits -> g_w
// ---------------------------------------------------------------------------
__global__ void softmax3_kernel(const float* __restrict__ att) {
    if (threadIdx.x == 0) {
        float a0 = att[0], a1 = att[1], a2 = att[2];
        float m  = fmaxf(a0, fmaxf(a1, a2));
        float e0 = expf(a0 - m), e1 = expf(a1 - m), e2 = expf(a2 - m);
        float s  = e0 + e1 + e2;
        g_w[0] = e0 / s; g_w[1] = e1 / s; g_w[2] = e2 / s;
    }
}

// ---------------------------------------------------------------------------
// CSR build: zero counts -> histogram -> scan (3 kernels) -> placement
// ---------------------------------------------------------------------------
__global__ void zero_int_kernel(int* __restrict__ p, int n) {
    for (int i = blockIdx.x * blockDim.x + threadIdx.x; i < n;
         i += gridDim.x * blockDim.x)
        p[i] = 0;
}

__global__ void hist_kernel(const int* __restrict__ rows, int* __restrict__ cnt,
                            int nnz) {
    for (int i = blockIdx.x * blockDim.x + threadIdx.x; i < nnz;
         i += gridDim.x * blockDim.x)
        atomicAdd(&cnt[rows[i]], 1);
}

// per-tile sums (block of 1024, tile of 2048)
__global__ void tilesum_kernel(const int* __restrict__ cnt, int* __restrict__ tsum,
                               int n) {
    __shared__ int wsum[32];
    int base = blockIdx.x * SCAN_TILE;
    int v = 0;
    for (int i = threadIdx.x; i < SCAN_TILE; i += blockDim.x) {
        int idx = base + i;
        if (idx < n) v += cnt[idx];
    }
    int lane = threadIdx.x & 31, wid = threadIdx.x >> 5;
    for (int d = 16; d; d >>= 1) v += __shfl_down_sync(~0u, v, d);
    if (lane == 0) wsum[wid] = v;
    __syncthreads();
    if (wid == 0) {
        int w = wsum[lane];
        for (int d = 16; d; d >>= 1) w += __shfl_down_sync(~0u, w, d);
        if (lane == 0) tsum[blockIdx.x] = w;
    }
}

// exclusive scan of tile sums (tiny: <= 49 tiles), serial in one thread
__global__ void scantsum_kernel(int* __restrict__ tsum, int ntiles) {
    if (threadIdx.x == 0) {
        int run = 0;
        for (int i = 0; i < ntiles; i++) { int v = tsum[i]; tsum[i] = run; run += v; }
        tsum[ntiles] = run;
    }
}

// per-tile exclusive scan + tile offset -> offs (and cursor copy)
__global__ void scanfinal_kernel(const int* __restrict__ cnt,
                                 const int* __restrict__ toff,
                                 int* __restrict__ offs, int* __restrict__ cur,
                                 int n, int ntiles) {
    __shared__ int wsum[32];
    int tile = blockIdx.x;
    int base = tile * SCAN_TILE;
    int t = threadIdx.x;
    int i0 = base + 2 * t, i1 = i0 + 1;
    int a = (i0 < n) ? cnt[i0] : 0;
    int b = (i1 < n) ? cnt[i1] : 0;
    int s = a + b;
    int lane = t & 31, wid = t >> 5;
    int x = s;                                 // inclusive warp scan
    for (int d = 1; d < 32; d <<= 1) {
        int y = __shfl_up_sync(~0u, x, d);
        if (lane >= d) x += y;
    }
    if (lane == 31) wsum[wid] = x;
    __syncthreads();
    if (wid == 0) {
        int w = wsum[lane];
        int xx = w;
        for (int d = 1; d < 32; d <<= 1) {
            int y = __shfl_up_sync(~0u, xx, d);
            if (lane >= d) xx += y;
        }
        wsum[lane] = xx - w;                   // exclusive warp offsets
    }
    __syncthreads();
    int excl = (x - s) + wsum[wid] + toff[tile];
    if (i0 < n) { offs[i0] = excl;     cur[i0] = excl; }
    if (i1 < n) { offs[i1] = excl + a; cur[i1] = excl + a; }
    if (tile == 0 && t == 0) offs[n] = toff[ntiles];
}

// scatter edges into CSR slots (order within a row is arbitrary; fp-tolerant)
__global__ void place_kernel(const int* __restrict__ rows,
                             const int* __restrict__ cols,
                             const float* __restrict__ vals,
                             int* __restrict__ cur,
                             int* __restrict__ cols_r, float* __restrict__ vals_r,
                             int nnz) {
    for (int i = blockIdx.x * blockDim.x + threadIdx.x; i < nnz;
         i += gridDim.x * blockDim.x) {
        int r = rows[i];
        int p = atomicAdd(&cur[r], 1);
        cols_r[p] = cols[i];
        vals_r[p] = vals[i];
    }
}

// ---------------------------------------------------------------------------
// Gather-only CSR SpMM, warp-per-row, fused epilogues.
//   MODE 0: out[r] = acc                                   (tar spmm)
//   MODE 1: embs1[r] = (relu(acc)*d1 + pois)*d2            (layer-1 src spmm)
//   MODE 2: out[r] = w0*pois + w1*e1 + w2*((relu(acc)*d1+e1)*d2)
// ---------------------------------------------------------------------------
template <int MODE>
__global__ void __launch_bounds__(256)
spmm_csr_kernel(float4* __restrict__ out, const float* __restrict__ dense,
                const int* __restrict__ offs, const int* __restrict__ cols,
                const float* __restrict__ vals, int nrows,
                const float4* __restrict__ pois, const float4* __restrict__ e1in,
                const float4* __restrict__ d1, const float4* __restrict__ d2) {
    const int lane = threadIdx.x & 31;
    int warp = (blockIdx.x * blockDim.x + threadIdx.x) >> 5;
    const int nw = (gridDim.x * blockDim.x) >> 5;

    for (int r = warp; r < nrows; r += nw) {
        const int start = offs[r];
        const int end   = offs[r + 1];

        float4 a0 = make_float4(0.f, 0.f, 0.f, 0.f);
        float4 a1 = make_float4(0.f, 0.f, 0.f, 0.f);

        int j0 = start;
        // full-warp chunks: branch-free inner loop, good MLP
        for (; j0 + 32 <= end; j0 += 32) {
            const int   c = cols[j0 + lane];
            const float v = vals[j0 + lane];
            #pragma unroll 4
            for (int k = 0; k < 32; k++) {
                const int   ck = __shfl_sync(0xffffffffu, c, k);
                const float vk = __shfl_sync(0xffffffffu, v, k);
                const float4* __restrict__ s =
                    reinterpret_cast<const float4*>(dense + (size_t)ck * D) + lane;
                float4 x0 = __ldg(s);
                float4 x1 = __ldg(s + 32);
                a0.x += x0.x * vk; a0.y += x0.y * vk;
                a0.z += x0.z * vk; a0.w += x0.w * vk;
                a1.x += x1.x * vk; a1.y += x1.y * vk;
                a1.z += x1.z * vk; a1.w += x1.w * vk;
            }
        }
        if (j0 < end) {                         // tail chunk
            int j = j0 + lane;
            int   c = 0;
            float v = 0.f;
            if (j < end) { c = cols[j]; v = vals[j]; }
            const int cnt = end - j0;
            for (int k = 0; k < cnt; k++) {
                const int   ck = __shfl_sync(0xffffffffu, c, k);
                const float vk = __shfl_sync(0xffffffffu, v, k);
                const float4* __restrict__ s =
                    reinterpret_cast<const float4*>(dense + (size_t)ck * D) + lane;
                float4 x0 = __ldg(s);
                float4 x1 = __ldg(s + 32);
                a0.x += x0.x * vk; a0.y += x0.y * vk;
                a0.z += x0.z * vk; a0.w += x0.w * vk;
                a1.x += x1.x * vk; a1.y += x1.y * vk;
                a1.z += x1.z * vk; a1.w += x1.w * vk;
            }
        }

        const size_t o0 = (size_t)r * D4 + lane;
        const size_t o1 = o0 + 32;

        if (MODE == 0) {
            out[o0] = a0;
            out[o1] = a1;
        } else if (MODE == 1) {
            float4 p0 = pois[o0], p1 = pois[o1];
            float4 m0 = d1[o0],   m1 = d1[o1];
            float4 n0 = d2[o0],   n1 = d2[o1];
            float4 r0, r1;
            r0.x = (fmaxf(a0.x, 0.f) * m0.x + p0.x) * n0.x;
            r0.y = (fmaxf(a0.y, 0.f) * m0.y + p0.y) * n0.y;
            r0.z = (fmaxf(a0.z, 0.f) * m0.z + p0.z) * n0.z;
            r0.w = (fmaxf(a0.w, 0.f) * m0.w + p0.w) * n0.w;
            r1.x = (fmaxf(a1.x, 0.f) * m1.x + p1.x) * n1.x;
            r1.y = (fmaxf(a1.y, 0.f) * m1.y + p1.y) * n1.y;
            r1.z = (fmaxf(a1.z, 0.f) * m1.z + p1.z) * n1.z;
            r1.w = (fmaxf(a1.w, 0.f) * m1.w + p1.w) * n1.w;
            out[o0] = r0;
            out[o1] = r1;
        } else {
            const float w0 = g_w[0], w1 = g_w[1], w2 = g_w[2];
            float4 p0 = pois[o0], p1 = pois[o1];
            float4 e0 = e1in[o0], e1v = e1in[o1];
            float4 m0 = d1[o0],   m1 = d1[o1];
            float4 n0 = d2[o0],   n1 = d2[o1];
            float4 r0, r1;
            r0.x = w0 * p0.x + w1 * e0.x + w2 * ((fmaxf(a0.x, 0.f) * m0.x + e0.x) * n0.x);
            r0.y = w0 * p0.y + w1 * e0.y + w2 * ((fmaxf(a0.y, 0.f) * m0.y + e0.y) * n0.y);
            r0.z = w0 * p0.z + w1 * e0.z + w2 * ((fmaxf(a0.z, 0.f) * m0.z + e0.z) * n0.z);
            r0.w = w0 * p0.w + w1 * e0.w + w2 * ((fmaxf(a0.w, 0.f) * m0.w + e0.w) * n0.w);
            r1.x = w0 * p1.x + w1 * e1v.x + w2 * ((fmaxf(a1.x, 0.f) * m1.x + e1v.x) * n1.x);
            r1.y = w0 * p1.y + w1 * e1v.y + w2 * ((fmaxf(a1.y, 0.f) * m1.y + e1v.y) * n1.y);
            r1.z = w0 * p1.z + w1 * e1v.z + w2 * ((fmaxf(a1.z, 0.f) * m1.z + e1v.z) * n1.z);
            r1.w = w0 * p1.w + w1 * e1v.w + w2 * ((fmaxf(a1.w, 0.f) * m1.w + e1v.w) * n1.w);
            out[o0] = r0;
            out[o1] = r1;
        }
    }
}

// ---------------------------------------------------------------------------
// kernel_launch — graph-capturable, allocation-free
// ---------------------------------------------------------------------------
extern "C" void kernel_launch(void* const* d_in, const int* in_sizes, int n_in,
                              void* d_out, int out_size) {
    const float* pois     = (const float*)d_in[0];
    const float* tar_vals = (const float*)d_in[1];
    const float* src_vals = (const float*)d_in[2];
    const float* att      = (const float*)d_in[3];
    const float* drop1    = (const float*)d_in[4];   // [2, NP, D]
    const float* drop2    = (const float*)d_in[5];   // [2, NP, D]
    const int*   tar_rows = (const int*)d_in[6];
    const int*   tar_cols = (const int*)d_in[7];
    const int*   src_rows = (const int*)d_in[8];
    const int*   src_cols = (const int*)d_in[9];
    float4* out = (float4*)d_out;

    int *p_offs_t, *p_cur_t, *p_offs_s, *p_cur_s, *p_tsum;
    int *p_cols_t, *p_cols_s;
    float *p_vals_t, *p_vals_s, *p_mt, *p_e1;
    cudaGetSymbolAddress((void**)&p_offs_t, g_offs_t);
    cudaGetSymbolAddress((void**)&p_cur_t,  g_cur_t);
    cudaGetSymbolAddress((void**)&p_offs_s, g_offs_s);
    cudaGetSymbolAddress((void**)&p_cur_s,  g_cur_s);
    cudaGetSymbolAddress((void**)&p_tsum,   g_tsum);
    cudaGetSymbolAddress((void**)&p_cols_t, g_cols_t);
    cudaGetSymbolAddress((void**)&p_vals_t, g_vals_t);
    cudaGetSymbolAddress((void**)&p_cols_s, g_cols_s);
    cudaGetSymbolAddress((void**)&p_vals_s, g_vals_s);
    cudaGetSymbolAddress((void**)&p_mt,     g_msg_tar);
    cudaGetSymbolAddress((void**)&p_e1,     g_embs1);

    const int HB = 1024, HT = 256;     // hist / place grids
    const int nt_t = (NH + SCAN_TILE - 1) / SCAN_TILE;   // 25
    const int nt_s = (NP + SCAN_TILE - 1) / SCAN_TILE;   // 49

    softmax3_kernel<<<1, 32>>>(att);

    // ---- build CSR for tar matrix (rows in [0,NH)) ----
    zero_int_kernel<<<64, 256>>>(p_cur_t, NH + 1);
    hist_kernel<<<HB, HT>>>(tar_rows, p_cur_t, NNZC);
    tilesum_kernel<<<nt_t, 1024>>>(p_cur_t, p_tsum, NH);
    scantsum_kernel<<<1, 32>>>(p_tsum, nt_t);
    scanfinal_kernel<<<nt_t, 1024>>>(p_cur_t, p_tsum, p_offs_t, p_cur_t, NH, nt_t);
    place_kernel<<<HB, HT>>>(tar_rows, tar_cols, tar_vals, p_cur_t,
                             p_cols_t, p_vals_t, NNZC);

    // ---- build CSR for src matrix (rows in [0,NP)) ----
    zero_int_kernel<<<64, 256>>>(p_cur_s, NP + 1);
    hist_kernel<<<HB, HT>>>(src_rows, p_cur_s, NNZC);
    tilesum_kernel<<<nt_s, 1024>>>(p_cur_s, p_tsum, NP);
    scantsum_kernel<<<1, 32>>>(p_tsum, nt_s);
    scanfinal_kernel<<<nt_s, 1024>>>(p_cur_s, p_tsum, p_offs_s, p_cur_s, NP, nt_s);
    place_kernel<<<HB, HT>>>(src_rows, src_cols, src_vals, p_cur_s,
                             p_cols_s, p_vals_s, NNZC);

    const int BT = 256;                       // 8 warps / block
    const int GB_T = (NH + 7) / 8;            // warp per hyperedge row
    const int GB_S = (NP + 7) / 8;            // warp per poi row
    const size_t ND = (size_t)NP * D;

    // ---- layer 1 ----
    spmm_csr_kernel<0><<<GB_T, BT>>>((float4*)p_mt, pois, p_offs_t, p_cols_t,
                                     p_vals_t, NH, nullptr, nullptr, nullptr, nullptr);
    spmm_csr_kernel<1><<<GB_S, BT>>>((float4*)p_e1, p_mt, p_offs_s, p_cols_s,
                                     p_vals_s, NP, (const float4*)pois, nullptr,
                                     (const float4*)drop1, (const float4*)drop2);

    // ---- layer 2 ----
    spmm_csr_kernel<0><<<GB_T, BT>>>((float4*)p_mt, p_e1, p_offs_t, p_cols_t,
                                     p_vals_t, NH, nullptr, nullptr, nullptr, nullptr);
    spmm_csr_kernel<2><<<GB_S, BT>>>(out, p_mt, p_offs_s, p_cols_s,
                                     p_vals_s, NP, (const float4*)pois,
                                     (const float4*)p_e1,
                                     (const float4*)(drop1 + ND),
                                     (const float4*)(drop2 + ND));
}

// round 13
// speedup vs baseline: 3.0263x; 1.2850x over previous
#include <cuda_runtime.h>
#include <cuda_fp16.h>
#include <cstdint>

// Problem constants (fixed by the reference)
constexpr int D    = 256;
constexpr int D4   = 64;       // float4 per row
constexpr int NP   = 100000;   // n_pois
constexpr int NH   = 50000;    // n_hyperedges
constexpr int NNZC = 1600000;  // nnz

constexpr int SCAN_TILE = 2048;    // elements per scan tile (1024 thr x 2)

// ---------------------------------------------------------------------------
// Scratch: __device__ globals (no cudaMalloc allowed)
// ---------------------------------------------------------------------------
__device__ int   g_offs_t[NH + 1];
__device__ int   g_cur_t [NH + 1];
__device__ int   g_offs_s[NP + 1];
__device__ int   g_cur_s [NP + 1];
__device__ int   g_tsum  [128];

__device__ int   g_cols_t[NNZC];
__device__ float g_vals_t[NNZC];
__device__ int   g_cols_s[NNZC];
__device__ float g_vals_s[NNZC];

__device__ __half g_pois_h  [(size_t)NP * D];  // 51.2 MB fp16 gather copy of pois
__device__ __half g_msg_tar_h[(size_t)NH * D]; // 25.6 MB fp16 tar-spmm output
__device__ float  g_embs1   [(size_t)NP * D];  // 102.4 MB exact embs1
__device__ __half g_embs1_h [(size_t)NP * D];  // 51.2 MB fp16 gather copy of embs1
__device__ float  g_w[3];

// ---------------------------------------------------------------------------
// softmax over the 3 layer-attention logits -> g_w
// ---------------------------------------------------------------------------
__global__ void softmax3_kernel(const float* __restrict__ att) {
    if (threadIdx.x == 0) {
        float a0 = att[0], a1 = att[1], a2 = att[2];
        float m  = fmaxf(a0, fmaxf(a1, a2));
        float e0 = expf(a0 - m), e1 = expf(a1 - m), e2 = expf(a2 - m);
        float s  = e0 + e1 + e2;
        g_w[0] = e0 / s; g_w[1] = e1 / s; g_w[2] = e2 / s;
    }
}

// ---------------------------------------------------------------------------
// fp32 -> fp16 convert (float4 in, 4 halves out per thread)
// ---------------------------------------------------------------------------
__global__ void f2h_kernel(const float4* __restrict__ in, uint2* __restrict__ out,
                           int n4) {
    for (int i = blockIdx.x * blockDim.x + threadIdx.x; i < n4;
         i += gridDim.x * blockDim.x) {
        float4 v = in[i];
        __half2 h0 = __float22half2_rn(make_float2(v.x, v.y));
        __half2 h1 = __float22half2_rn(make_float2(v.z, v.w));
        uint2 r;
        r.x = *reinterpret_cast<uint32_t*>(&h0);
        r.y = *reinterpret_cast<uint32_t*>(&h1);
        out[i] = r;
    }
}

// ---------------------------------------------------------------------------
// CSR build: zero counts -> histogram -> scan (3 kernels) -> placement
// ---------------------------------------------------------------------------
__global__ void zero_int_kernel(int* __restrict__ p, int n) {
    for (int i = blockIdx.x * blockDim.x + threadIdx.x; i < n;
         i += gridDim.x * blockDim.x)
        p[i] = 0;
}

__global__ void hist_kernel(const int* __restrict__ rows, int* __restrict__ cnt,
                            int nnz) {
    for (int i = blockIdx.x * blockDim.x + threadIdx.x; i < nnz;
         i += gridDim.x * blockDim.x)
        atomicAdd(&cnt[rows[i]], 1);
}

// per-tile sums (block of 1024, tile of 2048)
__global__ void tilesum_kernel(const int* __restrict__ cnt, int* __restrict__ tsum,
                               int n) {
    __shared__ int wsum[32];
    int base = blockIdx.x * SCAN_TILE;
    int v = 0;
    for (int i = threadIdx.x; i < SCAN_TILE; i += blockDim.x) {
        int idx = base + i;
        if (idx < n) v += cnt[idx];
    }
    int lane = threadIdx.x & 31, wid = threadIdx.x >> 5;
    for (int d = 16; d; d >>= 1) v += __shfl_down_sync(~0u, v, d);
    if (lane == 0) wsum[wid] = v;
    __syncthreads();
    if (wid == 0) {
        int w = wsum[lane];
        for (int d = 16; d; d >>= 1) w += __shfl_down_sync(~0u, w, d);
        if (lane == 0) tsum[blockIdx.x] = w;
    }
}

// exclusive scan of tile sums (tiny: <= 49 tiles), serial in one thread
__global__ void scantsum_kernel(int* __restrict__ tsum, int ntiles) {
    if (threadIdx.x == 0) {
        int run = 0;
        for (int i = 0; i < ntiles; i++) { int v = tsum[i]; tsum[i] = run; run += v; }
        tsum[ntiles] = run;
    }
}

// per-tile exclusive scan + tile offset -> offs (and cursor copy)
__global__ void scanfinal_kernel(const int* __restrict__ cnt,
                                 const int* __restrict__ toff,
                                 int* __restrict__ offs, int* __restrict__ cur,
                                 int n, int ntiles) {
    __shared__ int wsum[32];
    int tile = blockIdx.x;
    int base = tile * SCAN_TILE;
    int t = threadIdx.x;
    int i0 = base + 2 * t, i1 = i0 + 1;
    int a = (i0 < n) ? cnt[i0] : 0;
    int b = (i1 < n) ? cnt[i1] : 0;
    int s = a + b;
    int lane = t & 31, wid = t >> 5;
    int x = s;                                 // inclusive warp scan
    for (int d = 1; d < 32; d <<= 1) {
        int y = __shfl_up_sync(~0u, x, d);
        if (lane >= d) x += y;
    }
    if (lane == 31) wsum[wid] = x;
    __syncthreads();
    if (wid == 0) {
        int w = wsum[lane];
        int xx = w;
        for (int d = 1; d < 32; d <<= 1) {
            int y = __shfl_up_sync(~0u, xx, d);
            if (lane >= d) xx += y;
        }
        wsum[lane] = xx - w;                   // exclusive warp offsets
    }
    __syncthreads();
    int excl = (x - s) + wsum[wid] + toff[tile];
    if (i0 < n) { offs[i0] = excl;     cur[i0] = excl; }
    if (i1 < n) { offs[i1] = excl + a; cur[i1] = excl + a; }
    if (tile == 0 && t == 0) offs[n] = toff[ntiles];
}

// scatter edges into CSR slots (order within a row is arbitrary; fp-tolerant)
__global__ void place_kernel(const int* __restrict__ rows,
                             const int* __restrict__ cols,
                             const float* __restrict__ vals,
                             int* __restrict__ cur,
                             int* __restrict__ cols_r, float* __restrict__ vals_r,
                             int nnz) {
    for (int i = blockIdx.x * blockDim.x + threadIdx.x; i < nnz;
         i += gridDim.x * blockDim.x) {
        int r = rows[i];
        int p = atomicAdd(&cur[r], 1);
        cols_r[p] = cols[i];
        vals_r[p] = vals[i];
    }
}

// ---------------------------------------------------------------------------
// Gather-only CSR SpMM over fp16 dense rows, fp32 accumulate, warp-per-row.
//   MODE 0: msg_tar_h[r] = (half)acc                       (tar spmm)
//   MODE 1: embs1[r] = (relu(acc)*d1 + pois)*d2  (fp32 + fp16 copies)
//   MODE 2: out[r] = w0*pois + w1*e1 + w2*((relu(acc)*d1+e1)*d2)
// Each lane owns cols [4*lane, 4*lane+4) and [128+4*lane, 128+4*lane+4).
// fp16 row = 512B: lane loads uint2 (8B) at +8*lane and +8*lane+256.
// ---------------------------------------------------------------------------
__device__ __forceinline__ void acc_half4(float4& a, uint32_t lo, uint32_t hi,
                                          float vk) {
    __half2 h0 = *reinterpret_cast<__half2*>(&lo);
    __half2 h1 = *reinterpret_cast<__half2*>(&hi);
    float2 f0 = __half22float2(h0);
    float2 f1 = __half22float2(h1);
    a.x += f0.x * vk; a.y += f0.y * vk;
    a.z += f1.x * vk; a.w += f1.y * vk;
}

template <int MODE>
__global__ void __launch_bounds__(256)
spmm_csr_kernel(float4* __restrict__ out, uint2* __restrict__ outh,
                const __half* __restrict__ dense,
                const int* __restrict__ offs, const int* __restrict__ cols,
                const float* __restrict__ vals, int nrows,
                const float4* __restrict__ pois, const float4* __restrict__ e1in,
                const float4* __restrict__ d1, const float4* __restrict__ d2) {
    const int lane = threadIdx.x & 31;
    int warp = (blockIdx.x * blockDim.x + threadIdx.x) >> 5;
    const int nw = (gridDim.x * blockDim.x) >> 5;

    for (int r = warp; r < nrows; r += nw) {
        const int start = offs[r];
        const int end   = offs[r + 1];

        float4 a0 = make_float4(0.f, 0.f, 0.f, 0.f);
        float4 a1 = make_float4(0.f, 0.f, 0.f, 0.f);

        int j0 = start;
        for (; j0 + 32 <= end; j0 += 32) {          // full-warp chunks
            const int   c = cols[j0 + lane];
            const float v = vals[j0 + lane];
            #pragma unroll 4
            for (int k = 0; k < 32; k++) {
                const int   ck = __shfl_sync(0xffffffffu, c, k);
                const float vk = __shfl_sync(0xffffffffu, v, k);
                const uint2* __restrict__ s =
                    reinterpret_cast<const uint2*>(dense + (size_t)ck * D) + lane;
                uint2 x0 = __ldg(s);
                uint2 x1 = __ldg(s + 32);
                acc_half4(a0, x0.x, x0.y, vk);
                acc_half4(a1, x1.x, x1.y, vk);
            }
        }
        if (j0 < end) {                              // tail chunk
            int j = j0 + lane;
            int   c = 0;
            float v = 0.f;
            if (j < end) { c = cols[j]; v = vals[j]; }
            const int cnt = end - j0;
            for (int k = 0; k < cnt; k++) {
                const int   ck = __shfl_sync(0xffffffffu, c, k);
                const float vk = __shfl_sync(0xffffffffu, v, k);
                const uint2* __restrict__ s =
                    reinterpret_cast<const uint2*>(dense + (size_t)ck * D) + lane;
                uint2 x0 = __ldg(s);
                uint2 x1 = __ldg(s + 32);
                acc_half4(a0, x0.x, x0.y, vk);
                acc_half4(a1, x1.x, x1.y, vk);
            }
        }

        const size_t o0 = (size_t)r * D4 + lane;
        const size_t o1 = o0 + 32;

        if (MODE == 0) {
            __half2 p00 = __float22half2_rn(make_float2(a0.x, a0.y));
            __half2 p01 = __float22half2_rn(make_float2(a0.z, a0.w));
            __half2 p10 = __float22half2_rn(make_float2(a1.x, a1.y));
            __half2 p11 = __float22half2_rn(make_float2(a1.z, a1.w));
            uint2 h0, h1;
            h0.x = *reinterpret_cast<uint32_t*>(&p00);
            h0.y = *reinterpret_cast<uint32_t*>(&p01);
            h1.x = *reinterpret_cast<uint32_t*>(&p10);
            h1.y = *reinterpret_cast<uint32_t*>(&p11);
            outh[o0] = h0;
            outh[o1] = h1;
        } else if (MODE == 1) {
            float4 p0 = pois[o0], p1 = pois[o1];
            float4 m0 = d1[o0],   m1 = d1[o1];
            float4 n0 = d2[o0],   n1 = d2[o1];
            float4 r0, r1;
            r0.x = (fmaxf(a0.x, 0.f) * m0.x + p0.x) * n0.x;
            r0.y = (fmaxf(a0.y, 0.f) * m0.y + p0.y) * n0.y;
            r0.z = (fmaxf(a0.z, 0.f) * m0.z + p0.z) * n0.z;
            r0.w = (fmaxf(a0.w, 0.f) * m0.w + p0.w) * n0.w;
            r1.x = (fmaxf(a1.x, 0.f) * m1.x + p1.x) * n1.x;
            r1.y = (fmaxf(a1.y, 0.f) * m1.y + p1.y) * n1.y;
            r1.z = (fmaxf(a1.z, 0.f) * m1.z + p1.z) * n1.z;
            r1.w = (fmaxf(a1.w, 0.f) * m1.w + p1.w) * n1.w;
            out[o0] = r0;
            out[o1] = r1;
            // fp16 gather copy for the layer-2 tar spmm
            __half2 q00 = __float22half2_rn(make_float2(r0.x, r0.y));
            __half2 q01 = __float22half2_rn(make_float2(r0.z, r0.w));
            __half2 q10 = __float22half2_rn(make_float2(r1.x, r1.y));
            __half2 q11 = __float22half2_rn(make_float2(r1.z, r1.w));
            uint2 h0, h1;
            h0.x = *reinterpret_cast<uint32_t*>(&q00);
            h0.y = *reinterpret_cast<uint32_t*>(&q01);
            h1.x = *reinterpret_cast<uint32_t*>(&q10);
            h1.y = *reinterpret_cast<uint32_t*>(&q11);
            outh[o0] = h0;
            outh[o1] = h1;
        } else {
            const float w0 = g_w[0], w1 = g_w[1], w2 = g_w[2];
            float4 p0 = pois[o0], p1 = pois[o1];
            float4 e0 = e1in[o0], e1v = e1in[o1];
            float4 m0 = d1[o0],   m1 = d1[o1];
            float4 n0 = d2[o0],   n1 = d2[o1];
            float4 r0, r1;
            r0.x = w0 * p0.x + w1 * e0.x + w2 * ((fmaxf(a0.x, 0.f) * m0.x + e0.x) * n0.x);
            r0.y = w0 * p0.y + w1 * e0.y + w2 * ((fmaxf(a0.y, 0.f) * m0.y + e0.y) * n0.y);
            r0.z = w0 * p0.z + w1 * e0.z + w2 * ((fmaxf(a0.z, 0.f) * m0.z + e0.z) * n0.z);
            r0.w = w0 * p0.w + w1 * e0.w + w2 * ((fmaxf(a0.w, 0.f) * m0.w + e0.w) * n0.w);
            r1.x = w0 * p1.x + w1 * e1v.x + w2 * ((fmaxf(a1.x, 0.f) * m1.x + e1v.x) * n1.x);
            r1.y = w0 * p1.y + w1 * e1v.y + w2 * ((fmaxf(a1.y, 0.f) * m1.y + e1v.y) * n1.y);
            r1.z = w0 * p1.z + w1 * e1v.z + w2 * ((fmaxf(a1.z, 0.f) * m1.z + e1v.z) * n1.z);
            r1.w = w0 * p1.w + w1 * e1v.w + w2 * ((fmaxf(a1.w, 0.f) * m1.w + e1v.w) * n1.w);
            out[o0] = r0;
            out[o1] = r1;
        }
    }
}

// ---------------------------------------------------------------------------
// kernel_launch — graph-capturable, allocation-free
// ---------------------------------------------------------------------------
extern "C" void kernel_launch(void* const* d_in, const int* in_sizes, int n_in,
                              void* d_out, int out_size) {
    const float* pois     = (const float*)d_in[0];
    const float* tar_vals = (const float*)d_in[1];
    const float* src_vals = (const float*)d_in[2];
    const float* att      = (const float*)d_in[3];
    const float* drop1    = (const float*)d_in[4];   // [2, NP, D]
    const float* drop2    = (const float*)d_in[5];   // [2, NP, D]
    const int*   tar_rows = (const int*)d_in[6];
    const int*   tar_cols = (const int*)d_in[7];
    const int*   src_rows = (const int*)d_in[8];
    const int*   src_cols = (const int*)d_in[9];
    float4* out = (float4*)d_out;

    int *p_offs_t, *p_cur_t, *p_offs_s, *p_cur_s, *p_tsum;
    int *p_cols_t, *p_cols_s;
    float *p_vals_t, *p_vals_s, *p_e1;
    __half *p_pois_h, *p_mt_h, *p_e1_h;
    cudaGetSymbolAddress((void**)&p_offs_t, g_offs_t);
    cudaGetSymbolAddress((void**)&p_cur_t,  g_cur_t);
    cudaGetSymbolAddress((void**)&p_offs_s, g_offs_s);
    cudaGetSymbolAddress((void**)&p_cur_s,  g_cur_s);
    cudaGetSymbolAddress((void**)&p_tsum,   g_tsum);
    cudaGetSymbolAddress((void**)&p_cols_t, g_cols_t);
    cudaGetSymbolAddress((void**)&p_vals_t, g_vals_t);
    cudaGetSymbolAddress((void**)&p_cols_s, g_cols_s);
    cudaGetSymbolAddress((void**)&p_vals_s, g_vals_s);
    cudaGetSymbolAddress((void**)&p_pois_h, g_pois_h);
    cudaGetSymbolAddress((void**)&p_mt_h,   g_msg_tar_h);
    cudaGetSymbolAddress((void**)&p_e1,     g_embs1);
    cudaGetSymbolAddress((void**)&p_e1_h,   g_embs1_h);

    const int HB = 1024, HT = 256;     // hist / place grids
    const int nt_t = (NH + SCAN_TILE - 1) / SCAN_TILE;   // 25
    const int nt_s = (NP + SCAN_TILE - 1) / SCAN_TILE;   // 49

    softmax3_kernel<<<1, 32>>>(att);

    // fp16 copy of pois for layer-1 tar gather
    f2h_kernel<<<2048, 256>>>((const float4*)pois, (uint2*)p_pois_h, NP * D / 4);

    // ---- build CSR for tar matrix (rows in [0,NH)) ----
    zero_int_kernel<<<64, 256>>>(p_cur_t, NH + 1);
    hist_kernel<<<HB, HT>>>(tar_rows, p_cur_t, NNZC);
    tilesum_kernel<<<nt_t, 1024>>>(p_cur_t, p_tsum, NH);
    scantsum_kernel<<<1, 32>>>(p_tsum, nt_t);
    scanfinal_kernel<<<nt_t, 1024>>>(p_cur_t, p_tsum, p_offs_t, p_cur_t, NH, nt_t);
    place_kernel<<<HB, HT>>>(tar_rows, tar_cols, tar_vals, p_cur_t,
                             p_cols_t, p_vals_t, NNZC);

    // ---- build CSR for src matrix (rows in [0,NP)) ----
    zero_int_kernel<<<64, 256>>>(p_cur_s, NP + 1);
    hist_kernel<<<HB, HT>>>(src_rows, p_cur_s, NNZC);
    tilesum_kernel<<<nt_s, 1024>>>(p_cur_s, p_tsum, NP);
    scantsum_kernel<<<1, 32>>>(p_tsum, nt_s);
    scanfinal_kernel<<<nt_s, 1024>>>(p_cur_s, p_tsum, p_offs_s, p_cur_s, NP, nt_s);
    place_kernel<<<HB, HT>>>(src_rows, src_cols, src_vals, p_cur_s,
                             p_cols_s, p_vals_s, NNZC);

    const int BT = 256;                       // 8 warps / block
    const int GB_T = (NH + 7) / 8;            // warp per hyperedge row
    const int GB_S = (NP + 7) / 8;            // warp per poi row
    const size_t ND = (size_t)NP * D;

    // ---- layer 1 ----
    spmm_csr_kernel<0><<<GB_T, BT>>>(nullptr, (uint2*)p_mt_h, p_pois_h,
                                     p_offs_t, p_cols_t, p_vals_t, NH,
                                     nullptr, nullptr, nullptr, nullptr);
    spmm_csr_kernel<1><<<GB_S, BT>>>((float4*)p_e1, (uint2*)p_e1_h, p_mt_h,
                                     p_offs_s, p_cols_s, p_vals_s, NP,
                                     (const float4*)pois, nullptr,
                                     (const float4*)drop1, (const float4*)drop2);

    // ---- layer 2 ----
    spmm_csr_kernel<0><<<GB_T, BT>>>(nullptr, (uint2*)p_mt_h, p_e1_h,
                                     p_offs_t, p_cols_t, p_vals_t, NH,
                                     nullptr, nullptr, nullptr, nullptr);
    spmm_csr_kernel<2><<<GB_S, BT>>>(out, nullptr, p_mt_h,
                                     p_offs_s, p_cols_s, p_vals_s, NP,
                                     (const float4*)pois, (const float4*)p_e1,
                                     (const float4*)(drop1 + ND),
                                     (const float4*)(drop2 + ND));
}